// round 11
// baseline (speedup 1.0000x reference)
#include <cuda_runtime.h>
#include <cuda_bf16.h>
#include <cstring>
#include <cstdint>

using u64 = unsigned long long;
using u32 = unsigned int;

#define CIN     32
#define COUT    64
#define OZ      100
#define OY      100
#define OX      8
#define NUM_OUT (2*OZ*OY*OX)               /* 160000 */
#define N_MAX   400000
#define REGION  400128                     /* per-offset region, 256-aligned */
#define GRID_GEMM 444

/* ------------------ device scratch (static, no allocs) ------------------ */
__device__ int      g_hist[65536];         /* self-clearing in select_pass */
__device__ int      g_sel[2];
__device__ unsigned g_thr;
__device__ int      g_cursor[27];          /* self-clearing in mask_out */
__device__ int      g_keep[NUM_OUT];       /* self-clearing in mask_out */
__device__ int      g_pair_idx[27 * REGION];
__device__ int      g_pair_vox[27 * REGION];
__device__ u64      g_fhi[N_MAX * 8];      /* pre-split features, fragment layout */
__device__ u64      g_flo[N_MAX * 8];

/* ------------------ generic helpers ------------------ */
__device__ __forceinline__ unsigned fkey(float x) {
    unsigned u = __float_as_uint(x);
    return (u & 0x80000000u) ? ~u : (u | 0x80000000u);
}

/* enumerate valid (offset, output voxel) pairs for one point: <= 8 */
__device__ __forceinline__ int enum_off(int b, int z, int y, int x, int* ol, int* vl) {
    int zo[2], zc[2]; int nzc = 0;
    int yo[2], yc[2]; int nyc = 0;
    int xo[2], xc[2]; int nxc = 0;
#pragma unroll
    for (int o = 0; o < 3; o++) {
        int nz = z + 1 - o;
        if (nz >= 0 && !(nz & 1)) { int c = nz >> 1; if (c < OZ) { zo[nzc] = o; zc[nzc] = c; nzc++; } }
        int ny = y + 1 - o;
        if (ny >= 0 && !(ny & 1)) { int c = ny >> 1; if (c < OY) { yo[nyc] = o; yc[nyc] = c; nyc++; } }
        int nx = x + 1 - o;
        if (nx >= 0 && !(nx & 1)) { int c = nx >> 1; if (c < OX) { xo[nxc] = o; xc[nxc] = c; nxc++; } }
    }
    int cnt = 0;
    for (int iz = 0; iz < nzc; iz++)
        for (int iy = 0; iy < nyc; iy++)
            for (int ix = 0; ix < nxc; ix++) {
                ol[cnt] = (zo[iz]*3 + yo[iy])*3 + xo[ix];
                vl[cnt] = ((b*OZ + zc[iz])*OY + yc[iy])*OX + xc[ix];
                cnt++;
            }
    return cnt;
}

/* ------------------ bf16 split helper ------------------ */
__device__ __forceinline__ void split2(float x, float y, u32& hi, u32& lo) {
    __nv_bfloat162 h2 = __floats2bfloat162_rn(x, y);
    float rx = x - __bfloat162float(h2.x);
    float ry = y - __bfloat162float(h2.y);
    __nv_bfloat162 l2 = __floats2bfloat162_rn(rx, ry);
    memcpy(&hi, &h2, 4);
    memcpy(&lo, &l2, 4);
}

/* ------------------ kernel (side stream): pre-split features --------------- */
/* entry p = kf*4+iq of row idx holds cols (16kf+2iq, +1) | (16kf+2iq+8, +1)  */
__global__ void split_feat(const float* __restrict__ F, int n) {
    int t = blockIdx.x * blockDim.x + threadIdx.x;
    if (t >= n * 8) return;
    int idx = t >> 3;
    int p   = t & 7;
    int kf  = p >> 2;
    int iq  = p & 3;
    int c0  = 16 * kf + 2 * iq;
    float2 fa = *(const float2*)(F + idx * CIN + c0);
    float2 fb = *(const float2*)(F + idx * CIN + c0 + 8);
    u32 ha, la, hb, lb;
    split2(fa.x, fa.y, ha, la);
    split2(fb.x, fb.y, hb, lb);
    g_fhi[t] = ((u64)hb << 32) | ha;
    g_flo[t] = ((u64)lb << 32) | la;
}

/* ------------------ kernel: fill rulebook + mask histogram ------------------ */
__global__ void fill_hist(const int* __restrict__ coors, const float* __restrict__ mask, int n) {
    __shared__ int s[27];
    __shared__ int sbase[27];
    if (threadIdx.x < 27) s[threadIdx.x] = 0;
    __syncthreads();
    int i = blockIdx.x * blockDim.x + threadIdx.x;
    int ol[8], vl[8], rk[8];
    int cnt = 0;
    if (i < n) {
        atomicAdd(&g_hist[fkey(mask[i]) >> 16], 1);
        int4 c = ((const int4*)coors)[i];
        cnt = enum_off(c.x, c.y, c.z, c.w, ol, vl);
        for (int e = 0; e < cnt; e++) rk[e] = atomicAdd(&s[ol[e]], 1);
    }
    __syncthreads();
    if (threadIdx.x < 27) {
        int c = s[threadIdx.x];
        sbase[threadIdx.x] = c ? atomicAdd(&g_cursor[threadIdx.x], c) : 0;
    }
    __syncthreads();
    if (i < n) {
        for (int e = 0; e < cnt; e++) {
            int pos = ol[e] * REGION + sbase[ol[e]] + rk[e];
            g_pair_idx[pos] = i;
            g_pair_vox[pos] = vl[e];
        }
    }
}

/* ------------------ radix select pass (self-clearing) ------------------ */
__global__ void select_pass(int pass, int k) {
    __shared__ int s[1024];
    int t = threadIdx.x;
    const int4* h4 = (const int4*)&g_hist[t * 64];
    int sum = 0;
#pragma unroll
    for (int j = 0; j < 16; j++) {
        int4 v = h4[j];
        sum += v.x + v.y + v.z + v.w;
    }
    s[t] = sum;
    __syncthreads();
    for (int off = 1; off < 1024; off <<= 1) {
        int v = (t >= off) ? s[t - off] : 0;
        __syncthreads();
        s[t] += v;
        __syncthreads();
    }
    int rank = (pass == 0) ? k : g_sel[1];
    int incl = s[t];
    int excl = incl - sum;
    if (rank >= excl && rank < incl) {
        int cum = excl;
        int bin = t * 64;
        for (int j = 0; j < 64; j++) {
            int h = g_hist[t * 64 + j];
            if (rank < cum + h) { bin = t * 64 + j; break; }
            cum += h;
        }
        if (pass == 0) { g_sel[0] = bin; g_sel[1] = rank - cum; }
        else           { g_thr = ((unsigned)g_sel[0] << 16) | (unsigned)bin; }
    }
    int4* w4 = (int4*)&g_hist[t * 64];
#pragma unroll
    for (int j = 0; j < 16; j++) w4[j] = make_int4(0, 0, 0, 0);
}

#define MMA16816(C0,C1,C2,C3, A0,A1,A2,A3, B0,B1) \
    asm volatile("mma.sync.aligned.m16n8k16.row.col.f32.bf16.bf16.f32 " \
                 "{%0,%1,%2,%3}, {%4,%5,%6,%7}, {%8,%9}, {%0,%1,%2,%3};" \
                 : "+f"(C0), "+f"(C1), "+f"(C2), "+f"(C3) \
                 : "r"(A0), "r"(A1), "r"(A2), "r"(A3), "r"(B0), "r"(B1))

#define EMIT_TILE(C0,C1,C2,C3, VA, VB, J)                                       \
    {                                                                           \
        u64 p01 = ((u64)__float_as_uint(C1) << 32) | (u64)__float_as_uint(C0);  \
        u64 p23 = ((u64)__float_as_uint(C3) << 32) | (u64)__float_as_uint(C2);  \
        u64 q01 = __shfl_xor_sync(0xFFFFFFFFu, p01, 1);                         \
        u64 q23 = __shfl_xor_sync(0xFFFFFFFFu, p23, 1);                         \
        if (!(iq & 1)) {                                                        \
            int col = 8 * (J) + 2 * iq;                                         \
            if ((VA) >= 0) {                                                    \
                float* dst = out + (size_t)(VA) * COUT + col;                   \
                asm volatile("red.global.add.v4.f32 [%0], {%1, %2, %3, %4};"    \
                             :: "l"(dst), "f"(C0), "f"(C1),                     \
                                "f"(__uint_as_float((u32)q01)),                 \
                                "f"(__uint_as_float((u32)(q01 >> 32)))          \
                             : "memory");                                       \
            }                                                                   \
            if ((VB) >= 0) {                                                    \
                float* dst = out + (size_t)(VB) * COUT + col;                   \
                asm volatile("red.global.add.v4.f32 [%0], {%1, %2, %3, %4};"    \
                             :: "l"(dst), "f"(C2), "f"(C3),                     \
                                "f"(__uint_as_float((u32)q23)),                 \
                                "f"(__uint_as_float((u32)(q23 >> 32)))          \
                             : "memory");                                       \
            }                                                                   \
        }                                                                       \
    }

/* fetch pre-split A fragment pair for one row/kf */
__device__ __forceinline__ void loadAF(int idx, int kf, int iq,
                                       u32& h0, u32& h2, u32& l0, u32& l2) {
    if (idx < 0) { h0 = h2 = l0 = l2 = 0u; return; }
    u64 h = g_fhi[idx * 8 + kf * 4 + iq];
    u64 l = g_flo[idx * 8 + kf * 4 + iq];
    h0 = (u32)h; h2 = (u32)(h >> 32);
    l0 = (u32)l; l2 = (u32)(l >> 32);
}

/* ------------------ persistent HMMA GEMM ------------------ */
__global__ __launch_bounds__(256, 3)
void gemm_mma(const float* __restrict__ W, float* __restrict__ out) {
    __shared__ int sprefix[28];
    __shared__ int scnt[27];
    __shared__ u64 sbhi[8][2][32];
    __shared__ u64 sblo[8][2][32];

    int tid  = threadIdx.x;
    int wid  = tid >> 5;
    int lane = tid & 31;
    int g    = lane >> 2;
    int iq   = lane & 3;

    if (tid == 0) {
        int a = 0;
        for (int o = 0; o < 27; o++) {
            int c = g_cursor[o];
            scnt[o] = c;
            sprefix[o] = a;
            a += (c + 255) >> 8;
        }
        sprefix[27] = a;
    }
    __syncthreads();
    int total = sprefix[27];

    int per = (total + gridDim.x - 1) / gridDim.x;
    int rc0 = blockIdx.x * per;
    int rc1 = min(rc0 + per, total);

    int prev_o = -1;

    for (int rc = rc0; rc < rc1; rc++) {
        int o = 0;
#pragma unroll
        for (int j = 1; j < 27; j++) if (sprefix[j] <= rc) o = j;
        int ws  = (rc - sprefix[o]) << 8;
        int cnt = scnt[o];

        if (o != prev_o) {
            __syncthreads();
            const float* Wo = W + o * (CIN * COUT);
            for (int e = tid; e < 512; e += 256) {
                int j  = e >> 6;
                int kf = (e >> 5) & 1;
                int l  = e & 31;
                int gg = l >> 2, qq = l & 3;
                int nn = 8 * j + gg;
                int m0 = 8 * kf + qq;
                int m1 = m0 + 4;
                float w00 = Wo[(2*m0    ) * COUT + nn];
                float w01 = Wo[(2*m0 + 1) * COUT + nn];
                float w10 = Wo[(2*m1    ) * COUT + nn];
                float w11 = Wo[(2*m1 + 1) * COUT + nn];
                u32 h0, l0, h1, l1;
                split2(w00, w01, h0, l0);
                split2(w10, w11, h1, l1);
                sbhi[j][kf][l] = ((u64)h1 << 32) | h0;
                sblo[j][kf][l] = ((u64)l1 << 32) | l0;
            }
            __syncthreads();
            prev_o = o;
        }

        int gs = ws + wid * 32;
        if (gs >= cnt) continue;
        int navail = cnt - gs;
        int pbase = o * REGION + gs;

        int pidx = -1, pvox = -1;
        if (lane < navail) { pidx = g_pair_idx[pbase + lane]; pvox = g_pair_vox[pbase + lane]; }
        int i0  = __shfl_sync(0xFFFFFFFFu, pidx, g);
        int i8  = __shfl_sync(0xFFFFFFFFu, pidx, g + 8);
        int i16 = __shfl_sync(0xFFFFFFFFu, pidx, g + 16);
        int i24 = __shfl_sync(0xFFFFFFFFu, pidx, g + 24);
        int v0  = __shfl_sync(0xFFFFFFFFu, pvox, g);
        int v8  = __shfl_sync(0xFFFFFFFFu, pvox, g + 8);
        int v16 = __shfl_sync(0xFFFFFFFFu, pvox, g + 16);
        int v24 = __shfl_sync(0xFFFFFFFFu, pvox, g + 24);

        u32 ah0[2][4], al0[2][4], ah1[2][4], al1[2][4];
#pragma unroll
        for (int kf = 0; kf < 2; kf++) {
            loadAF(i0,  kf, iq, ah0[kf][0], ah0[kf][2], al0[kf][0], al0[kf][2]);
            loadAF(i8,  kf, iq, ah0[kf][1], ah0[kf][3], al0[kf][1], al0[kf][3]);
            loadAF(i16, kf, iq, ah1[kf][0], ah1[kf][2], al1[kf][0], al1[kf][2]);
            loadAF(i24, kf, iq, ah1[kf][1], ah1[kf][3], al1[kf][1], al1[kf][3]);
        }

#pragma unroll
        for (int j = 0; j < 8; j++) {
            float c00 = 0.f, c01 = 0.f, c02 = 0.f, c03 = 0.f;
            float c10 = 0.f, c11 = 0.f, c12 = 0.f, c13 = 0.f;
#pragma unroll
            for (int kf = 0; kf < 2; kf++) {
                u64 vh = sbhi[j][kf][lane];
                u64 vl = sblo[j][kf][lane];
                u32 bh0 = (u32)vh, bh1 = (u32)(vh >> 32);
                u32 bl0 = (u32)vl, bl1 = (u32)(vl >> 32);
                MMA16816(c00,c01,c02,c03, ah0[kf][0],ah0[kf][1],ah0[kf][2],ah0[kf][3], bh0, bh1);
                MMA16816(c00,c01,c02,c03, ah0[kf][0],ah0[kf][1],ah0[kf][2],ah0[kf][3], bl0, bl1);
                MMA16816(c00,c01,c02,c03, al0[kf][0],al0[kf][1],al0[kf][2],al0[kf][3], bh0, bh1);
                MMA16816(c10,c11,c12,c13, ah1[kf][0],ah1[kf][1],ah1[kf][2],ah1[kf][3], bh0, bh1);
                MMA16816(c10,c11,c12,c13, ah1[kf][0],ah1[kf][1],ah1[kf][2],ah1[kf][3], bl0, bl1);
                MMA16816(c10,c11,c12,c13, al1[kf][0],al1[kf][1],al1[kf][2],al1[kf][3], bh0, bh1);
            }
            EMIT_TILE(c00,c01,c02,c03, v0,  v8,  j);
            EMIT_TILE(c10,c11,c12,c13, v16, v24, j);
        }
    }
}

/* ------------------ low-16 histogram ------------------ */
__global__ void hist_low16(const float* __restrict__ mask, int n) {
    int i = blockIdx.x * blockDim.x + threadIdx.x;
    if (i < n) {
        unsigned u = fkey(mask[i]);
        if ((int)(u >> 16) == g_sel[0]) atomicAdd(&g_hist[u & 0xFFFFu], 1);
    }
}

/* ------------------ mark kept voxels ------------------ */
__global__ void mark_keep(const int* __restrict__ coors, const float* __restrict__ mask, int n) {
    int i = blockIdx.x * blockDim.x + threadIdx.x;
    if (i >= n) return;
    if (fkey(mask[i]) < g_thr) return;
    int4 c = ((const int4*)coors)[i];
    int ol[8], vl[8];
    int cnt = enum_off(c.x, c.y, c.z, c.w, ol, vl);
    for (int e = 0; e < cnt; e++) g_keep[vl[e]] = 1;
}

/* ------------------ zero non-kept rows; self-clear keep + cursors ---------- */
__global__ void mask_out(float* __restrict__ out) {
    int v = blockIdx.x * blockDim.x + threadIdx.x;
    if (v < 27) g_cursor[v] = 0;
    if (v >= NUM_OUT) return;
    if (g_keep[v]) {
        g_keep[v] = 0;
    } else {
        float4 z = make_float4(0.f, 0.f, 0.f, 0.f);
        float4* d = (float4*)(out + (size_t)v * COUT);
#pragma unroll
        for (int j = 0; j < 16; j++) d[j] = z;
    }
}

/* ------------------ launch: two side streams, fork-join capture ------------- */
extern "C" void kernel_launch(void* const* d_in, const int* in_sizes, int n_in,
                              void* d_out, int out_size) {
    const float* F = (const float*)d_in[0];   /* features [N,32] */
    const int*   C = (const int*)  d_in[1];   /* coors    [N,4]  */
    const float* M = (const float*)d_in[2];   /* mask     [N]    */
    const float* W = (const float*)d_in[3];   /* weight   [3,3,3,32,64] */
    float* out = (float*)d_out;

    int n = in_sizes[2];
    int k = (int)((double)n * 0.5);
    int gpts = (n + 255) / 256;

    static cudaStream_t s2 = ([]{
        cudaStream_t s; cudaStreamCreateWithFlags(&s, cudaStreamNonBlocking); return s;
    })();
    static cudaStream_t s3 = ([]{
        cudaStream_t s; cudaStreamCreateWithFlags(&s, cudaStreamNonBlocking); return s;
    })();
    static cudaEvent_t evStart = ([]{
        cudaEvent_t e; cudaEventCreateWithFlags(&e, cudaEventDisableTiming); return e;
    })();
    static cudaEvent_t evFork = ([]{
        cudaEvent_t e; cudaEventCreateWithFlags(&e, cudaEventDisableTiming); return e;
    })();
    static cudaEvent_t evPre = ([]{
        cudaEvent_t e; cudaEventCreateWithFlags(&e, cudaEventDisableTiming); return e;
    })();
    static cudaEvent_t evJoin = ([]{
        cudaEvent_t e; cudaEventCreateWithFlags(&e, cudaEventDisableTiming); return e;
    })();

    /* fork s3 at start: feature pre-split + output memset (off critical path) */
    cudaEventRecord(evStart, 0);
    cudaStreamWaitEvent(s3, evStart, 0);
    split_feat<<<(n * 8 + 255) / 256, 256, 0, s3>>>(F, n);
    cudaMemsetAsync(out, 0, (size_t)out_size * sizeof(float), s3);
    cudaEventRecord(evPre, s3);

    /* main: rulebook build */
    fill_hist<<<gpts, 256>>>(C, M, n);

    /* fork s2: threshold/keep chain, concurrent with GEMM */
    cudaEventRecord(evFork, 0);
    cudaStreamWaitEvent(s2, evFork, 0);
    select_pass<<<1, 1024, 0, s2>>>(0, k);
    hist_low16<<<gpts, 256, 0, s2>>>(M, n);
    select_pass<<<1, 1024, 0, s2>>>(1, 0);
    mark_keep<<<gpts, 256, 0, s2>>>(C, M, n);
    cudaEventRecord(evJoin, s2);

    /* main: GEMM (needs rulebook + pre-split features + zeroed out) */
    cudaStreamWaitEvent(0, evPre, 0);
    gemm_mma<<<GRID_GEMM, 256>>>(W, out);

    /* join, then final mask (self-clears keep + cursors for next replay) */
    cudaStreamWaitEvent(0, evJoin, 0);
    mask_out<<<(NUM_OUT + 255) / 256, 256>>>(out);
}

// round 13
// speedup vs baseline: 1.1288x; 1.1288x over previous
#include <cuda_runtime.h>
#include <cuda_bf16.h>
#include <cstring>
#include <cstdint>

using u64 = unsigned long long;
using u32 = unsigned int;

#define CIN     32
#define COUT    64
#define OZ      100
#define OY      100
#define OX      8
#define NUM_OUT (2*OZ*OY*OX)               /* 160000 */
#define REGION  400128                     /* per-offset region, 256-aligned */
#define GRID_GEMM 444

/* ------------------ device scratch (static, no allocs) ------------------ */
__device__ int      g_hist[65536];         /* self-clearing in select_pass */
__device__ int      g_sel[2];
__device__ unsigned g_thr;
__device__ int      g_cursor[27];          /* self-clearing in mask_out */
__device__ int      g_keep[NUM_OUT];       /* self-clearing in mask_out */
__device__ int2     g_pair[27 * REGION];   /* packed (idx, vox) */

/* ------------------ generic helpers ------------------ */
__device__ __forceinline__ unsigned fkey(float x) {
    unsigned u = __float_as_uint(x);
    return (u & 0x80000000u) ? ~u : (u | 0x80000000u);
}

/* enumerate valid (offset, output voxel) pairs for one point: <= 8 */
__device__ __forceinline__ int enum_off(int b, int z, int y, int x, int* ol, int* vl) {
    int zo[2], zc[2]; int nzc = 0;
    int yo[2], yc[2]; int nyc = 0;
    int xo[2], xc[2]; int nxc = 0;
#pragma unroll
    for (int o = 0; o < 3; o++) {
        int nz = z + 1 - o;
        if (nz >= 0 && !(nz & 1)) { int c = nz >> 1; if (c < OZ) { zo[nzc] = o; zc[nzc] = c; nzc++; } }
        int ny = y + 1 - o;
        if (ny >= 0 && !(ny & 1)) { int c = ny >> 1; if (c < OY) { yo[nyc] = o; yc[nyc] = c; nyc++; } }
        int nx = x + 1 - o;
        if (nx >= 0 && !(nx & 1)) { int c = nx >> 1; if (c < OX) { xo[nxc] = o; xc[nxc] = c; nxc++; } }
    }
    int cnt = 0;
    for (int iz = 0; iz < nzc; iz++)
        for (int iy = 0; iy < nyc; iy++)
            for (int ix = 0; ix < nxc; ix++) {
                ol[cnt] = (zo[iz]*3 + yo[iy])*3 + xo[ix];
                vl[cnt] = ((b*OZ + zc[iz])*OY + yc[iy])*OX + xc[ix];
                cnt++;
            }
    return cnt;
}

/* ------------------ kernel: fill rulebook + mask histogram ------------------ */
__global__ void fill_hist(const int* __restrict__ coors, const float* __restrict__ mask, int n) {
    __shared__ int s[27];
    __shared__ int sbase[27];
    if (threadIdx.x < 27) s[threadIdx.x] = 0;
    __syncthreads();
    int i = blockIdx.x * blockDim.x + threadIdx.x;
    int ol[8], vl[8], rk[8];
    int cnt = 0;
    if (i < n) {
        atomicAdd(&g_hist[fkey(mask[i]) >> 16], 1);
        int4 c = ((const int4*)coors)[i];
        cnt = enum_off(c.x, c.y, c.z, c.w, ol, vl);
        for (int e = 0; e < cnt; e++) rk[e] = atomicAdd(&s[ol[e]], 1);
    }
    __syncthreads();
    if (threadIdx.x < 27) {
        int c = s[threadIdx.x];
        sbase[threadIdx.x] = c ? atomicAdd(&g_cursor[threadIdx.x], c) : 0;
    }
    __syncthreads();
    if (i < n) {
        for (int e = 0; e < cnt; e++) {
            int pos = ol[e] * REGION + sbase[ol[e]] + rk[e];
            g_pair[pos] = make_int2(i, vl[e]);      /* single STG.64 */
        }
    }
}

/* ------------------ radix select pass (self-clearing) ------------------ */
__global__ void select_pass(int pass, int k) {
    __shared__ int s[1024];
    int t = threadIdx.x;
    const int4* h4 = (const int4*)&g_hist[t * 64];
    int sum = 0;
#pragma unroll
    for (int j = 0; j < 16; j++) {
        int4 v = h4[j];
        sum += v.x + v.y + v.z + v.w;
    }
    s[t] = sum;
    __syncthreads();
    for (int off = 1; off < 1024; off <<= 1) {
        int v = (t >= off) ? s[t - off] : 0;
        __syncthreads();
        s[t] += v;
        __syncthreads();
    }
    int rank = (pass == 0) ? k : g_sel[1];
    int incl = s[t];
    int excl = incl - sum;
    if (rank >= excl && rank < incl) {
        int cum = excl;
        int bin = t * 64;
        for (int j = 0; j < 64; j++) {
            int h = g_hist[t * 64 + j];
            if (rank < cum + h) { bin = t * 64 + j; break; }
            cum += h;
        }
        if (pass == 0) { g_sel[0] = bin; g_sel[1] = rank - cum; }
        else           { g_thr = ((unsigned)g_sel[0] << 16) | (unsigned)bin; }
    }
    int4* w4 = (int4*)&g_hist[t * 64];
#pragma unroll
    for (int j = 0; j < 16; j++) w4[j] = make_int4(0, 0, 0, 0);
}

/* ------------------ bf16 helpers ------------------ */
__device__ __forceinline__ void split2(float x, float y, u32& hi, u32& lo) {
    __nv_bfloat162 h2 = __floats2bfloat162_rn(x, y);
    float rx = x - __bfloat162float(h2.x);
    float ry = y - __bfloat162float(h2.y);
    __nv_bfloat162 l2 = __floats2bfloat162_rn(rx, ry);
    memcpy(&hi, &h2, 4);
    memcpy(&lo, &l2, 4);
}
__device__ __forceinline__ void loadA(const float* __restrict__ F, int idx, int col,
                                      u32& hi, u32& lo) {
    if (idx < 0) { hi = 0u; lo = 0u; return; }
    float2 f = *(const float2*)(F + idx * CIN + col);
    split2(f.x, f.y, hi, lo);
}
#define MMA16816(C0,C1,C2,C3, A0,A1,A2,A3, B0,B1) \
    asm volatile("mma.sync.aligned.m16n8k16.row.col.f32.bf16.bf16.f32 " \
                 "{%0,%1,%2,%3}, {%4,%5,%6,%7}, {%8,%9}, {%0,%1,%2,%3};" \
                 : "+f"(C0), "+f"(C1), "+f"(C2), "+f"(C3) \
                 : "r"(A0), "r"(A1), "r"(A2), "r"(A3), "r"(B0), "r"(B1))

#define EMIT_TILE(C0,C1,C2,C3, VA, VB, J)                                       \
    {                                                                           \
        u64 p01 = ((u64)__float_as_uint(C1) << 32) | (u64)__float_as_uint(C0);  \
        u64 p23 = ((u64)__float_as_uint(C3) << 32) | (u64)__float_as_uint(C2);  \
        u64 q01 = __shfl_xor_sync(0xFFFFFFFFu, p01, 1);                         \
        u64 q23 = __shfl_xor_sync(0xFFFFFFFFu, p23, 1);                         \
        if (!(iq & 1)) {                                                        \
            int col = 8 * (J) + 2 * iq;                                         \
            if ((VA) >= 0) {                                                    \
                float* dst = out + (size_t)(VA) * COUT + col;                   \
                asm volatile("red.global.add.v4.f32 [%0], {%1, %2, %3, %4};"    \
                             :: "l"(dst), "f"(C0), "f"(C1),                     \
                                "f"(__uint_as_float((u32)q01)),                 \
                                "f"(__uint_as_float((u32)(q01 >> 32)))          \
                             : "memory");                                       \
            }                                                                   \
            if ((VB) >= 0) {                                                    \
                float* dst = out + (size_t)(VB) * COUT + col;                   \
                asm volatile("red.global.add.v4.f32 [%0], {%1, %2, %3, %4};"    \
                             :: "l"(dst), "f"(C2), "f"(C3),                     \
                                "f"(__uint_as_float((u32)q23)),                 \
                                "f"(__uint_as_float((u32)(q23 >> 32)))          \
                             : "memory");                                       \
            }                                                                   \
        }                                                                       \
    }

/* ------------------ persistent HMMA GEMM (R10-proven core) ------------------ */
__global__ __launch_bounds__(256, 3)
void gemm_mma(const float* __restrict__ F, const float* __restrict__ W,
              float* __restrict__ out) {
    __shared__ int sprefix[28];
    __shared__ int scnt[27];
    __shared__ u64 sbhi[8][2][32];
    __shared__ u64 sblo[8][2][32];

    int tid  = threadIdx.x;
    int wid  = tid >> 5;
    int lane = tid & 31;
    int g    = lane >> 2;
    int iq   = lane & 3;

    if (tid == 0) {
        int a = 0;
        for (int o = 0; o < 27; o++) {
            int c = g_cursor[o];
            scnt[o] = c;
            sprefix[o] = a;
            a += (c + 255) >> 8;
        }
        sprefix[27] = a;
    }
    __syncthreads();
    int total = sprefix[27];

    int per = (total + gridDim.x - 1) / gridDim.x;
    int rc0 = blockIdx.x * per;
    int rc1 = min(rc0 + per, total);

    int prev_o = -1;

    for (int rc = rc0; rc < rc1; rc++) {
        int o = 0;
#pragma unroll
        for (int j = 1; j < 27; j++) if (sprefix[j] <= rc) o = j;
        int ws  = (rc - sprefix[o]) << 8;
        int cnt = scnt[o];

        if (o != prev_o) {
            __syncthreads();
            const float* Wo = W + o * (CIN * COUT);
            for (int e = tid; e < 512; e += 256) {
                int j  = e >> 6;
                int kf = (e >> 5) & 1;
                int l  = e & 31;
                int gg = l >> 2, qq = l & 3;
                int nn = 8 * j + gg;
                int m0 = 8 * kf + qq;
                int m1 = m0 + 4;
                float w00 = Wo[(2*m0    ) * COUT + nn];
                float w01 = Wo[(2*m0 + 1) * COUT + nn];
                float w10 = Wo[(2*m1    ) * COUT + nn];
                float w11 = Wo[(2*m1 + 1) * COUT + nn];
                u32 h0, l0, h1, l1;
                split2(w00, w01, h0, l0);
                split2(w10, w11, h1, l1);
                sbhi[j][kf][l] = ((u64)h1 << 32) | h0;
                sblo[j][kf][l] = ((u64)l1 << 32) | l0;
            }
            __syncthreads();
            prev_o = o;
        }

        int gs = ws + wid * 32;
        if (gs >= cnt) continue;
        int navail = cnt - gs;
        int pbase = o * REGION + gs;

        int pidx = -1, pvox = -1;
        if (lane < navail) {
            int2 pv = g_pair[pbase + lane];        /* single LDG.64 */
            pidx = pv.x; pvox = pv.y;
        }
        int i0  = __shfl_sync(0xFFFFFFFFu, pidx, g);
        int i8  = __shfl_sync(0xFFFFFFFFu, pidx, g + 8);
        int i16 = __shfl_sync(0xFFFFFFFFu, pidx, g + 16);
        int i24 = __shfl_sync(0xFFFFFFFFu, pidx, g + 24);
        int v0  = __shfl_sync(0xFFFFFFFFu, pvox, g);
        int v8  = __shfl_sync(0xFFFFFFFFu, pvox, g + 8);
        int v16 = __shfl_sync(0xFFFFFFFFu, pvox, g + 16);
        int v24 = __shfl_sync(0xFFFFFFFFu, pvox, g + 24);

        u32 ah0[2][4], al0[2][4], ah1[2][4], al1[2][4];
#pragma unroll
        for (int kf = 0; kf < 2; kf++) {
            int c0 = 16 * kf + 2 * iq;
            loadA(F, i0,  c0,     ah0[kf][0], al0[kf][0]);
            loadA(F, i8,  c0,     ah0[kf][1], al0[kf][1]);
            loadA(F, i0,  c0 + 8, ah0[kf][2], al0[kf][2]);
            loadA(F, i8,  c0 + 8, ah0[kf][3], al0[kf][3]);
            loadA(F, i16, c0,     ah1[kf][0], al1[kf][0]);
            loadA(F, i24, c0,     ah1[kf][1], al1[kf][1]);
            loadA(F, i16, c0 + 8, ah1[kf][2], al1[kf][2]);
            loadA(F, i24, c0 + 8, ah1[kf][3], al1[kf][3]);
        }

#pragma unroll
        for (int j = 0; j < 8; j++) {
            float c00 = 0.f, c01 = 0.f, c02 = 0.f, c03 = 0.f;
            float c10 = 0.f, c11 = 0.f, c12 = 0.f, c13 = 0.f;
#pragma unroll
            for (int kf = 0; kf < 2; kf++) {
                u64 vh = sbhi[j][kf][lane];
                u64 vl = sblo[j][kf][lane];
                u32 bh0 = (u32)vh, bh1 = (u32)(vh >> 32);
                u32 bl0 = (u32)vl, bl1 = (u32)(vl >> 32);
                MMA16816(c00,c01,c02,c03, ah0[kf][0],ah0[kf][1],ah0[kf][2],ah0[kf][3], bh0, bh1);
                MMA16816(c00,c01,c02,c03, ah0[kf][0],ah0[kf][1],ah0[kf][2],ah0[kf][3], bl0, bl1);
                MMA16816(c00,c01,c02,c03, al0[kf][0],al0[kf][1],al0[kf][2],al0[kf][3], bh0, bh1);
                MMA16816(c10,c11,c12,c13, ah1[kf][0],ah1[kf][1],ah1[kf][2],ah1[kf][3], bh0, bh1);
                MMA16816(c10,c11,c12,c13, ah1[kf][0],ah1[kf][1],ah1[kf][2],ah1[kf][3], bl0, bl1);
                MMA16816(c10,c11,c12,c13, al1[kf][0],al1[kf][1],al1[kf][2],al1[kf][3], bh0, bh1);
            }
            EMIT_TILE(c00,c01,c02,c03, v0,  v8,  j);
            EMIT_TILE(c10,c11,c12,c13, v16, v24, j);
        }
    }
}

/* ------------------ low-16 histogram ------------------ */
__global__ void hist_low16(const float* __restrict__ mask, int n) {
    int i = blockIdx.x * blockDim.x + threadIdx.x;
    if (i < n) {
        unsigned u = fkey(mask[i]);
        if ((int)(u >> 16) == g_sel[0]) atomicAdd(&g_hist[u & 0xFFFFu], 1);
    }
}

/* ------------------ mark kept voxels ------------------ */
__global__ void mark_keep(const int* __restrict__ coors, const float* __restrict__ mask, int n) {
    int i = blockIdx.x * blockDim.x + threadIdx.x;
    if (i >= n) return;
    if (fkey(mask[i]) < g_thr) return;
    int4 c = ((const int4*)coors)[i];
    int ol[8], vl[8];
    int cnt = enum_off(c.x, c.y, c.z, c.w, ol, vl);
    for (int e = 0; e < cnt; e++) g_keep[vl[e]] = 1;
}

/* ------------------ zero non-kept rows; self-clear keep + cursors ----------- */
__global__ void mask_out(float* __restrict__ out) {
    int v = blockIdx.x * blockDim.x + threadIdx.x;
    if (v < 27) g_cursor[v] = 0;
    if (v >= NUM_OUT) return;
    if (g_keep[v]) {
        g_keep[v] = 0;
    } else {
        float4 z = make_float4(0.f, 0.f, 0.f, 0.f);
        float4* d = (float4*)(out + (size_t)v * COUT);
#pragma unroll
        for (int j = 0; j < 16; j++) d[j] = z;
    }
}

/* ------------------ launch: fork-join capture ------------------ */
extern "C" void kernel_launch(void* const* d_in, const int* in_sizes, int n_in,
                              void* d_out, int out_size) {
    const float* F = (const float*)d_in[0];   /* features [N,32] */
    const int*   C = (const int*)  d_in[1];   /* coors    [N,4]  */
    const float* M = (const float*)d_in[2];   /* mask     [N]    */
    const float* W = (const float*)d_in[3];   /* weight   [3,3,3,32,64] */
    float* out = (float*)d_out;

    int n = in_sizes[2];
    int k = (int)((double)n * 0.5);
    int gpts = (n + 255) / 256;

    static cudaStream_t s2 = ([]{
        cudaStream_t s; cudaStreamCreateWithFlags(&s, cudaStreamNonBlocking); return s;
    })();
    static cudaStream_t s3 = ([]{
        cudaStream_t s; cudaStreamCreateWithFlags(&s, cudaStreamNonBlocking); return s;
    })();
    static cudaEvent_t evStart = ([]{
        cudaEvent_t e; cudaEventCreateWithFlags(&e, cudaEventDisableTiming); return e;
    })();
    static cudaEvent_t evFork = ([]{
        cudaEvent_t e; cudaEventCreateWithFlags(&e, cudaEventDisableTiming); return e;
    })();
    static cudaEvent_t evPre = ([]{
        cudaEvent_t e; cudaEventCreateWithFlags(&e, cudaEventDisableTiming); return e;
    })();
    static cudaEvent_t evJoin = ([]{
        cudaEvent_t e; cudaEventCreateWithFlags(&e, cudaEventDisableTiming); return e;
    })();

    /* s3: output memset only (8us DMA), hidden behind fill_hist */
    cudaEventRecord(evStart, 0);
    cudaStreamWaitEvent(s3, evStart, 0);
    cudaMemsetAsync(out, 0, (size_t)out_size * sizeof(float), s3);
    cudaEventRecord(evPre, s3);

    /* main: rulebook build */
    fill_hist<<<gpts, 256>>>(C, M, n);

    /* s2: threshold/keep chain, concurrent with GEMM */
    cudaEventRecord(evFork, 0);
    cudaStreamWaitEvent(s2, evFork, 0);
    select_pass<<<1, 1024, 0, s2>>>(0, k);
    hist_low16<<<gpts, 256, 0, s2>>>(M, n);
    select_pass<<<1, 1024, 0, s2>>>(1, 0);
    mark_keep<<<gpts, 256, 0, s2>>>(C, M, n);
    cudaEventRecord(evJoin, s2);

    /* main: GEMM (needs rulebook + zeroed out) */
    cudaStreamWaitEvent(0, evPre, 0);
    gemm_mma<<<GRID_GEMM, 256>>>(F, W, out);

    /* join, then final mask (self-clears keep + cursors for next replay) */
    cudaStreamWaitEvent(0, evJoin, 0);
    mask_out<<<(NUM_OUT + 255) / 256, 256>>>(out);
}

// round 14
// speedup vs baseline: 1.1333x; 1.0041x over previous
#include <cuda_runtime.h>
#include <cuda_bf16.h>
#include <cstring>
#include <cstdint>

using u64 = unsigned long long;
using u32 = unsigned int;

#define CIN     32
#define COUT    64
#define OZ      100
#define OY      100
#define OX      8
#define NUM_OUT (2*OZ*OY*OX)               /* 160000 */
#define REGION  400128                     /* per-offset region, 256-aligned */
#define GRID_GEMM 444

/* ------------------ device scratch (static, no allocs) ------------------ */
__device__ int      g_hist[65536];         /* self-clearing in select_pass */
__device__ int      g_sel[2];
__device__ unsigned g_thr;
__device__ int      g_cursor[27];          /* self-clearing in mask_out */
__device__ int      g_keep[NUM_OUT];       /* self-clearing in mask_out */
__device__ int2     g_pair[27 * REGION];   /* packed (idx, vox) */

/* ------------------ generic helpers ------------------ */
__device__ __forceinline__ unsigned fkey(float x) {
    unsigned u = __float_as_uint(x);
    return (u & 0x80000000u) ? ~u : (u | 0x80000000u);
}

/* enumerate valid (offset, output voxel) pairs for one point: <= 8 */
__device__ __forceinline__ int enum_off(int b, int z, int y, int x, int* ol, int* vl) {
    int zo[2], zc[2]; int nzc = 0;
    int yo[2], yc[2]; int nyc = 0;
    int xo[2], xc[2]; int nxc = 0;
#pragma unroll
    for (int o = 0; o < 3; o++) {
        int nz = z + 1 - o;
        if (nz >= 0 && !(nz & 1)) { int c = nz >> 1; if (c < OZ) { zo[nzc] = o; zc[nzc] = c; nzc++; } }
        int ny = y + 1 - o;
        if (ny >= 0 && !(ny & 1)) { int c = ny >> 1; if (c < OY) { yo[nyc] = o; yc[nyc] = c; nyc++; } }
        int nx = x + 1 - o;
        if (nx >= 0 && !(nx & 1)) { int c = nx >> 1; if (c < OX) { xo[nxc] = o; xc[nxc] = c; nxc++; } }
    }
    int cnt = 0;
    for (int iz = 0; iz < nzc; iz++)
        for (int iy = 0; iy < nyc; iy++)
            for (int ix = 0; ix < nxc; ix++) {
                ol[cnt] = (zo[iz]*3 + yo[iy])*3 + xo[ix];
                vl[cnt] = ((b*OZ + zc[iz])*OY + yc[iy])*OX + xc[ix];
                cnt++;
            }
    return cnt;
}

/* ------------------ kernel: fill rulebook + mask histogram ------------------ */
__global__ void fill_hist(const int* __restrict__ coors, const float* __restrict__ mask, int n) {
    __shared__ int s[27];
    __shared__ int sbase[27];
    if (threadIdx.x < 27) s[threadIdx.x] = 0;
    __syncthreads();
    int i = blockIdx.x * blockDim.x + threadIdx.x;
    int ol[8], vl[8], rk[8];
    int cnt = 0;
    if (i < n) {
        atomicAdd(&g_hist[fkey(mask[i]) >> 16], 1);
        int4 c = ((const int4*)coors)[i];
        cnt = enum_off(c.x, c.y, c.z, c.w, ol, vl);
        for (int e = 0; e < cnt; e++) rk[e] = atomicAdd(&s[ol[e]], 1);
    }
    __syncthreads();
    if (threadIdx.x < 27) {
        int c = s[threadIdx.x];
        sbase[threadIdx.x] = c ? atomicAdd(&g_cursor[threadIdx.x], c) : 0;
    }
    __syncthreads();
    if (i < n) {
        for (int e = 0; e < cnt; e++) {
            int pos = ol[e] * REGION + sbase[ol[e]] + rk[e];
            g_pair[pos] = make_int2(i, vl[e]);      /* single STG.64 */
        }
    }
}

/* ------------------ radix select pass (self-clearing) ------------------ */
__global__ void select_pass(int pass, int k) {
    __shared__ int s[1024];
    int t = threadIdx.x;
    const int4* h4 = (const int4*)&g_hist[t * 64];
    int sum = 0;
#pragma unroll
    for (int j = 0; j < 16; j++) {
        int4 v = h4[j];
        sum += v.x + v.y + v.z + v.w;
    }
    s[t] = sum;
    __syncthreads();
    for (int off = 1; off < 1024; off <<= 1) {
        int v = (t >= off) ? s[t - off] : 0;
        __syncthreads();
        s[t] += v;
        __syncthreads();
    }
    int rank = (pass == 0) ? k : g_sel[1];
    int incl = s[t];
    int excl = incl - sum;
    if (rank >= excl && rank < incl) {
        int cum = excl;
        int bin = t * 64;
        for (int j = 0; j < 64; j++) {
            int h = g_hist[t * 64 + j];
            if (rank < cum + h) { bin = t * 64 + j; break; }
            cum += h;
        }
        if (pass == 0) { g_sel[0] = bin; g_sel[1] = rank - cum; }
        else           { g_thr = ((unsigned)g_sel[0] << 16) | (unsigned)bin; }
    }
    int4* w4 = (int4*)&g_hist[t * 64];
#pragma unroll
    for (int j = 0; j < 16; j++) w4[j] = make_int4(0, 0, 0, 0);
}

/* ------------------ bf16 helpers ------------------ */
__device__ __forceinline__ void split2(float x, float y, u32& hi, u32& lo) {
    __nv_bfloat162 h2 = __floats2bfloat162_rn(x, y);
    float rx = x - __bfloat162float(h2.x);
    float ry = y - __bfloat162float(h2.y);
    __nv_bfloat162 l2 = __floats2bfloat162_rn(rx, ry);
    memcpy(&hi, &h2, 4);
    memcpy(&lo, &l2, 4);
}
/* one LDG.128: physical cols (col..col+3) carry frag slots a0 (x,y) and a2 (z,w)
   under the k-permutation shared with the B packing */
__device__ __forceinline__ void loadA4(const float* __restrict__ F, int idx, int col,
                                       u32& h01, u32& l01, u32& h23, u32& l23) {
    if (idx < 0) { h01 = l01 = h23 = l23 = 0u; return; }
    float4 f = *(const float4*)(F + idx * CIN + col);
    split2(f.x, f.y, h01, l01);
    split2(f.z, f.w, h23, l23);
}
#define MMA16816(C0,C1,C2,C3, A0,A1,A2,A3, B0,B1) \
    asm volatile("mma.sync.aligned.m16n8k16.row.col.f32.bf16.bf16.f32 " \
                 "{%0,%1,%2,%3}, {%4,%5,%6,%7}, {%8,%9}, {%0,%1,%2,%3};" \
                 : "+f"(C0), "+f"(C1), "+f"(C2), "+f"(C3) \
                 : "r"(A0), "r"(A1), "r"(A2), "r"(A3), "r"(B0), "r"(B1))

#define EMIT_TILE(C0,C1,C2,C3, VA, VB, J)                                       \
    {                                                                           \
        u64 p01 = ((u64)__float_as_uint(C1) << 32) | (u64)__float_as_uint(C0);  \
        u64 p23 = ((u64)__float_as_uint(C3) << 32) | (u64)__float_as_uint(C2);  \
        u64 q01 = __shfl_xor_sync(0xFFFFFFFFu, p01, 1);                         \
        u64 q23 = __shfl_xor_sync(0xFFFFFFFFu, p23, 1);                         \
        if (!(iq & 1)) {                                                        \
            int col = 8 * (J) + 2 * iq;                                         \
            if ((VA) >= 0) {                                                    \
                float* dst = out + (size_t)(VA) * COUT + col;                   \
                asm volatile("red.global.add.v4.f32 [%0], {%1, %2, %3, %4};"    \
                             :: "l"(dst), "f"(C0), "f"(C1),                     \
                                "f"(__uint_as_float((u32)q01)),                 \
                                "f"(__uint_as_float((u32)(q01 >> 32)))          \
                             : "memory");                                       \
            }                                                                   \
            if ((VB) >= 0) {                                                    \
                float* dst = out + (size_t)(VB) * COUT + col;                   \
                asm volatile("red.global.add.v4.f32 [%0], {%1, %2, %3, %4};"    \
                             :: "l"(dst), "f"(C2), "f"(C3),                     \
                                "f"(__uint_as_float((u32)q23)),                 \
                                "f"(__uint_as_float((u32)(q23 >> 32)))          \
                             : "memory");                                       \
            }                                                                   \
        }                                                                       \
    }

/* ------------------ persistent HMMA GEMM ------------------ */
__global__ __launch_bounds__(256, 3)
void gemm_mma(const float* __restrict__ F, const float* __restrict__ W,
              float* __restrict__ out) {
    __shared__ int sprefix[28];
    __shared__ int scnt[27];
    __shared__ u64 sbhi[8][2][32];
    __shared__ u64 sblo[8][2][32];

    int tid  = threadIdx.x;
    int wid  = tid >> 5;
    int lane = tid & 31;
    int g    = lane >> 2;
    int iq   = lane & 3;

    if (tid == 0) {
        int a = 0;
        for (int o = 0; o < 27; o++) {
            int c = g_cursor[o];
            scnt[o] = c;
            sprefix[o] = a;
            a += (c + 255) >> 8;
        }
        sprefix[27] = a;
    }
    __syncthreads();
    int total = sprefix[27];

    int per = (total + gridDim.x - 1) / gridDim.x;
    int rc0 = blockIdx.x * per;
    int rc1 = min(rc0 + per, total);

    int prev_o = -1;

    for (int rc = rc0; rc < rc1; rc++) {
        int o = 0;
#pragma unroll
        for (int j = 1; j < 27; j++) if (sprefix[j] <= rc) o = j;
        int ws  = (rc - sprefix[o]) << 8;
        int cnt = scnt[o];

        if (o != prev_o) {
            __syncthreads();
            const float* Wo = W + o * (CIN * COUT);
            for (int e = tid; e < 512; e += 256) {
                int j  = e >> 6;
                int kf = (e >> 5) & 1;
                int l  = e & 31;
                int gg = l >> 2, qq = l & 3;
                int nn = 8 * j + gg;
                /* k-permutation matching loadA4: frag b0 = physical rows
                   (16kf+4qq, +1), frag b1 = (16kf+4qq+2, +3) */
                int base = 16 * kf + 4 * qq;
                float w00 = Wo[(base    ) * COUT + nn];
                float w01 = Wo[(base + 1) * COUT + nn];
                float w10 = Wo[(base + 2) * COUT + nn];
                float w11 = Wo[(base + 3) * COUT + nn];
                u32 h0, l0, h1, l1;
                split2(w00, w01, h0, l0);
                split2(w10, w11, h1, l1);
                sbhi[j][kf][l] = ((u64)h1 << 32) | h0;
                sblo[j][kf][l] = ((u64)l1 << 32) | l0;
            }
            __syncthreads();
            prev_o = o;
        }

        int gs = ws + wid * 32;
        if (gs >= cnt) continue;
        int navail = cnt - gs;
        int pbase = o * REGION + gs;

        int pidx = -1, pvox = -1;
        if (lane < navail) {
            int2 pv = g_pair[pbase + lane];        /* single LDG.64 */
            pidx = pv.x; pvox = pv.y;
        }
        int i0  = __shfl_sync(0xFFFFFFFFu, pidx, g);
        int i8  = __shfl_sync(0xFFFFFFFFu, pidx, g + 8);
        int i16 = __shfl_sync(0xFFFFFFFFu, pidx, g + 16);
        int i24 = __shfl_sync(0xFFFFFFFFu, pidx, g + 24);
        int v0  = __shfl_sync(0xFFFFFFFFu, pvox, g);
        int v8  = __shfl_sync(0xFFFFFFFFu, pvox, g + 8);
        int v16 = __shfl_sync(0xFFFFFFFFu, pvox, g + 16);
        int v24 = __shfl_sync(0xFFFFFFFFu, pvox, g + 24);

        /* A fragments: one LDG.128 per (row, kf) under the k-permutation */
        u32 ah0[2][4], al0[2][4], ah1[2][4], al1[2][4];
#pragma unroll
        for (int kf = 0; kf < 2; kf++) {
            int c0 = 16 * kf + 4 * iq;
            loadA4(F, i0,  c0, ah0[kf][0], al0[kf][0], ah0[kf][2], al0[kf][2]);
            loadA4(F, i8,  c0, ah0[kf][1], al0[kf][1], ah0[kf][3], al0[kf][3]);
            loadA4(F, i16, c0, ah1[kf][0], al1[kf][0], ah1[kf][2], al1[kf][2]);
            loadA4(F, i24, c0, ah1[kf][1], al1[kf][1], ah1[kf][3], al1[kf][3]);
        }

#pragma unroll
        for (int j = 0; j < 8; j++) {
            float c00 = 0.f, c01 = 0.f, c02 = 0.f, c03 = 0.f;
            float c10 = 0.f, c11 = 0.f, c12 = 0.f, c13 = 0.f;
#pragma unroll
            for (int kf = 0; kf < 2; kf++) {
                u64 vh = sbhi[j][kf][lane];
                u64 vl = sblo[j][kf][lane];
                u32 bh0 = (u32)vh, bh1 = (u32)(vh >> 32);
                u32 bl0 = (u32)vl, bl1 = (u32)(vl >> 32);
                MMA16816(c00,c01,c02,c03, ah0[kf][0],ah0[kf][1],ah0[kf][2],ah0[kf][3], bh0, bh1);
                MMA16816(c00,c01,c02,c03, ah0[kf][0],ah0[kf][1],ah0[kf][2],ah0[kf][3], bl0, bl1);
                MMA16816(c00,c01,c02,c03, al0[kf][0],al0[kf][1],al0[kf][2],al0[kf][3], bh0, bh1);
                MMA16816(c10,c11,c12,c13, ah1[kf][0],ah1[kf][1],ah1[kf][2],ah1[kf][3], bh0, bh1);
                MMA16816(c10,c11,c12,c13, ah1[kf][0],ah1[kf][1],ah1[kf][2],ah1[kf][3], bl0, bl1);
                MMA16816(c10,c11,c12,c13, al1[kf][0],al1[kf][1],al1[kf][2],al1[kf][3], bh0, bh1);
            }
            EMIT_TILE(c00,c01,c02,c03, v0,  v8,  j);
            EMIT_TILE(c10,c11,c12,c13, v16, v24, j);
        }
    }
}

/* ------------------ low-16 histogram ------------------ */
__global__ void hist_low16(const float* __restrict__ mask, int n) {
    int i = blockIdx.x * blockDim.x + threadIdx.x;
    if (i < n) {
        unsigned u = fkey(mask[i]);
        if ((int)(u >> 16) == g_sel[0]) atomicAdd(&g_hist[u & 0xFFFFu], 1);
    }
}

/* ------------------ mark kept voxels ------------------ */
__global__ void mark_keep(const int* __restrict__ coors, const float* __restrict__ mask, int n) {
    int i = blockIdx.x * blockDim.x + threadIdx.x;
    if (i >= n) return;
    if (fkey(mask[i]) < g_thr) return;
    int4 c = ((const int4*)coors)[i];
    int ol[8], vl[8];
    int cnt = enum_off(c.x, c.y, c.z, c.w, ol, vl);
    for (int e = 0; e < cnt; e++) g_keep[vl[e]] = 1;
}

/* ------------------ zero non-kept rows; self-clear keep + cursors ----------- */
__global__ void mask_out(float* __restrict__ out) {
    int v = blockIdx.x * blockDim.x + threadIdx.x;
    if (v < 27) g_cursor[v] = 0;
    if (v >= NUM_OUT) return;
    if (g_keep[v]) {
        g_keep[v] = 0;
    } else {
        float4 z = make_float4(0.f, 0.f, 0.f, 0.f);
        float4* d = (float4*)(out + (size_t)v * COUT);
#pragma unroll
        for (int j = 0; j < 16; j++) d[j] = z;
    }
}

/* ------------------ launch: fork-join capture ------------------ */
extern "C" void kernel_launch(void* const* d_in, const int* in_sizes, int n_in,
                              void* d_out, int out_size) {
    const float* F = (const float*)d_in[0];   /* features [N,32] */
    const int*   C = (const int*)  d_in[1];   /* coors    [N,4]  */
    const float* M = (const float*)d_in[2];   /* mask     [N]    */
    const float* W = (const float*)d_in[3];   /* weight   [3,3,3,32,64] */
    float* out = (float*)d_out;

    int n = in_sizes[2];
    int k = (int)((double)n * 0.5);
    int gpts = (n + 255) / 256;

    static cudaStream_t s2 = ([]{
        cudaStream_t s; cudaStreamCreateWithFlags(&s, cudaStreamNonBlocking); return s;
    })();
    static cudaStream_t s3 = ([]{
        cudaStream_t s; cudaStreamCreateWithFlags(&s, cudaStreamNonBlocking); return s;
    })();
    static cudaEvent_t evStart = ([]{
        cudaEvent_t e; cudaEventCreateWithFlags(&e, cudaEventDisableTiming); return e;
    })();
    static cudaEvent_t evFork = ([]{
        cudaEvent_t e; cudaEventCreateWithFlags(&e, cudaEventDisableTiming); return e;
    })();
    static cudaEvent_t evPre = ([]{
        cudaEvent_t e; cudaEventCreateWithFlags(&e, cudaEventDisableTiming); return e;
    })();
    static cudaEvent_t evJoin = ([]{
        cudaEvent_t e; cudaEventCreateWithFlags(&e, cudaEventDisableTiming); return e;
    })();

    /* s3: output memset only (8us DMA), hidden behind fill_hist */
    cudaEventRecord(evStart, 0);
    cudaStreamWaitEvent(s3, evStart, 0);
    cudaMemsetAsync(out, 0, (size_t)out_size * sizeof(float), s3);
    cudaEventRecord(evPre, s3);

    /* main: rulebook build */
    fill_hist<<<gpts, 256>>>(C, M, n);

    /* s2: threshold/keep chain, concurrent with GEMM */
    cudaEventRecord(evFork, 0);
    cudaStreamWaitEvent(s2, evFork, 0);
    select_pass<<<1, 1024, 0, s2>>>(0, k);
    hist_low16<<<gpts, 256, 0, s2>>>(M, n);
    select_pass<<<1, 1024, 0, s2>>>(1, 0);
    mark_keep<<<gpts, 256, 0, s2>>>(C, M, n);
    cudaEventRecord(evJoin, s2);

    /* main: GEMM (needs rulebook + zeroed out) */
    cudaStreamWaitEvent(0, evPre, 0);
    gemm_mma<<<GRID_GEMM, 256>>>(F, W, out);

    /* join, then final mask (self-clears keep + cursors for next replay) */
    cudaStreamWaitEvent(0, evJoin, 0);
    mask_out<<<(NUM_OUT + 255) / 256, 256>>>(out);
}